// round 8
// baseline (speedup 1.0000x reference)
#include <cuda_runtime.h>
#include <cuda_bf16.h>

// Per-row histogram: x[4096,16384] fp32 -> out[4096,30] fp32 (permuted bin order).
//
// R6 change vs R5: two warps per row (half-row each) -> grid 2048 and
// __launch_bounds__(128,10) -> ~40 resident warps/SM (R5 had 25.6, occ 40%,
// and was warp-starved: DRAM stuck at 71.5% with issue 33%). Inner loop is
// unchanged R5 dataflow: zero smem, one-hot (1u<<bin) accumulated into 9
// register bit-plane counters via carry-save adders; epilogue = 32x32 warp
// bit-transpose + weighted popcounts, warp pairs combine through 512B smem.
//
// Bin math: t = fma(x,7/3,15); t = min(t,29); k = cvt.rmi.u32(t) (saturates
// negatives to 0 -> free lower clamp). 256 elem/lane, plane cap 511 -> the
// counters can never overflow, even adversarially.

#define NT    128     // 4 warps per CTA = 2 rows x 2 half-rows
#define COLS  16384
#define HALFC (COLS / 2)   // 8192 elements per warp, 256 per lane, 64 float4s
#define NBINS 30

__device__ __forceinline__ void csa(unsigned& sum, unsigned& carry,
                                    unsigned a, unsigned b, unsigned c) {
    unsigned u = a ^ b;
    sum   = u ^ c;                 // LOP3 0x96
    carry = (a & b) | (u & c);     // LOP3 0xE8
}

__device__ __forceinline__ unsigned bin_onehot(float v) {
    const float SCALE = 2.3333333333333335f;  // 7/3 = 1/binwidth
    const float OFF   = 15.0f;                // 1 - LO/w
    unsigned k = __float2uint_rd(fminf(fmaf(v, SCALE, OFF), 29.0f));
    return 1u << k;
}

// 32x32 bit-matrix transpose across a warp: lane b ends up holding bin b's
// per-lane bit vector.
__device__ __forceinline__ unsigned warp_bit_transpose(unsigned x, int lane) {
    #pragma unroll
    for (int st = 0; st < 5; st++) {
        const int s = 16 >> st;
        const unsigned m = (st == 0) ? 0x0000FFFFu :
                           (st == 1) ? 0x00FF00FFu :
                           (st == 2) ? 0x0F0F0F0Fu :
                           (st == 3) ? 0x33333333u : 0x55555555u;
        unsigned y = __shfl_xor_sync(0xffffffffu, x, s);
        x = (lane & s) ? ((x & ~m) | ((y & ~m) >> s))
                       : ((x &  m) | ((y &  m) << s));
    }
    return x;
}

__global__ __launch_bounds__(NT, 10)
void hist_kernel(const float* __restrict__ x, float* __restrict__ out) {
    const int lane = threadIdx.x & 31;
    const int warp = threadIdx.x >> 5;
    const int row  = blockIdx.x * 2 + (warp >> 1);  // 2 rows per CTA
    const int half = warp & 1;                      // which half-row

    const float4* __restrict__ p4 =
        reinterpret_cast<const float4*>(x + (size_t)row * COLS + half * HALFC) + lane;

    // 9 bit-plane counters: weights 1..256 (cap 511; <=256 elems/lane -> safe)
    unsigned ones = 0, twos = 0, fours = 0;
    unsigned a8 = 0, a16 = 0, a32 = 0, a64 = 0, a128 = 0, a256 = 0;

    // 64 float4s per lane, warp-stride 32 float4s (fully coalesced).
    #pragma unroll 2
    for (int i = 0; i < 64; i += 4) {
        float4 va = p4[(i + 0) * 32];
        float4 vb = p4[(i + 1) * 32];
        float4 vc = p4[(i + 2) * 32];
        float4 vd = p4[(i + 3) * 32];

        unsigned h0 = bin_onehot(va.x), h1 = bin_onehot(va.y);
        unsigned h2 = bin_onehot(va.z), h3 = bin_onehot(va.w);
        unsigned h4 = bin_onehot(vb.x), h5 = bin_onehot(vb.y);
        unsigned h6 = bin_onehot(vb.z), h7 = bin_onehot(vb.w);
        unsigned g0 = bin_onehot(vc.x), g1 = bin_onehot(vc.y);
        unsigned g2 = bin_onehot(vc.z), g3 = bin_onehot(vc.w);
        unsigned g4 = bin_onehot(vd.x), g5 = bin_onehot(vd.y);
        unsigned g6 = bin_onehot(vd.z), g7 = bin_onehot(vd.w);

        unsigned c2a, c2b, c4a, c4b, e8a, e8b;
        // block A: 8 one-hots -> weight-8 vector e8a
        csa(ones, c2a, ones, h0, h1);
        csa(ones, c2b, ones, h2, h3);
        csa(twos, c4a, twos, c2a, c2b);
        csa(ones, c2a, ones, h4, h5);
        csa(ones, c2b, ones, h6, h7);
        csa(twos, c4b, twos, c2a, c2b);
        csa(fours, e8a, fours, c4a, c4b);
        // block B: 8 one-hots -> weight-8 vector e8b
        csa(ones, c2a, ones, g0, g1);
        csa(ones, c2b, ones, g2, g3);
        csa(twos, c4a, twos, c2a, c2b);
        csa(ones, c2a, ones, g4, g5);
        csa(ones, c2b, ones, g6, g7);
        csa(twos, c4b, twos, c2a, c2b);
        csa(fours, e8b, fours, c4a, c4b);
        // merge weight-8 vectors, ripple carries up the planes
        unsigned c16;
        csa(a8, c16, a8, e8a, e8b);
        unsigned c = a16 & c16; a16 ^= c16;
        unsigned d = a32 & c;   a32 ^= c;
        c = a64 & d;   a64  ^= d;
        d = a128 & c;  a128 ^= c;
        a256 ^= d;
    }

    // Transpose planes so lane b holds bin b; weighted popcount -> count.
    unsigned planes[9] = {ones, twos, fours, a8, a16, a32, a64, a128, a256};
    unsigned cnt = 0;
    #pragma unroll
    for (int j = 0; j < 9; j++) {
        unsigned t = warp_bit_transpose(planes[j], lane);
        cnt += (unsigned)__popc(t) << j;
    }

    // Combine half-row counts through tiny smem; warp pair (2r, 2r+1) -> row.
    __shared__ unsigned sh[4][32];
    sh[warp][lane] = cnt;
    __syncthreads();
    if (half == 0 && lane < NBINS) {
        unsigned total = sh[warp][lane] + sh[warp + 1][lane];
        int pos = (lane == 0) ? 0 : (lane == NBINS - 1) ? 1 : (lane + 1);
        out[(size_t)row * NBINS + pos] = (float)total;
    }
}

extern "C" void kernel_launch(void* const* d_in, const int* in_sizes, int n_in,
                              void* d_out, int out_size) {
    const float* x = (const float*)d_in[0];
    float* out = (float*)d_out;
    int rows = in_sizes[0] / COLS;
    hist_kernel<<<rows / 2, NT>>>(x, out);
}

// round 9
// speedup vs baseline: 1.1166x; 1.1166x over previous
#include <cuda_runtime.h>
#include <cuda_bf16.h>
#include <cstdint>

// Per-row histogram: x[4096,16384] fp32 -> out[4096,30] fp32 (permuted order).
//
// R7: TMA (cp.async.bulk) producer pipeline. R1-R6 all plateaued at 65-71%
// DRAM regardless of occupancy / MLP tricks / smem-vs-register counting: the
// common factor was SM-issued LDGs. Here the TMA engine streams each row into
// a 4-stage x 8KB smem ring (mbarrier complete_tx); 128 threads consume each
// stage via 4x LDS.128 and the R5 register bit-plane CSA counters (8 planes,
// 128 elem/thread, cap 255 - unconditionally safe). ~3 pending stages x 6
// CTAs/SM = ~144KB outstanding per SM, decoupled from warp scheduling.
//
// Bin math: t = fma(x,7/3,15); t = min(t,29); k = cvt.rmi.u32(t) (cvt.rmi
// saturates negatives to 0 -> free lower clamp).

#define NT     128
#define COLS   16384
#define NBINS  30
#define STAGES 4
#define CHUNKB 8192                  // bytes per stage
#define CHUNKS (COLS * 4 / CHUNKB)   // 8 chunks per row

__device__ __forceinline__ uint32_t smem_u32(const void* p) {
    uint32_t a;
    asm("{ .reg .u64 t; cvta.to.shared.u64 t, %1; cvt.u32.u64 %0, t; }"
        : "=r"(a) : "l"(p));
    return a;
}

__device__ __forceinline__ void csa(unsigned& sum, unsigned& carry,
                                    unsigned a, unsigned b, unsigned c) {
    unsigned u = a ^ b;
    sum   = u ^ c;                 // LOP3 0x96
    carry = (a & b) | (u & c);     // LOP3 0xE8
}

__device__ __forceinline__ unsigned bin_onehot(float v) {
    const float SCALE = 2.3333333333333335f;  // 7/3 = 1/binwidth
    const float OFF   = 15.0f;                // 1 - LO/w
    return 1u << __float2uint_rd(fminf(fmaf(v, SCALE, OFF), 29.0f));
}

__device__ __forceinline__ unsigned warp_bit_transpose(unsigned x, int lane) {
    #pragma unroll
    for (int st = 0; st < 5; st++) {
        const int s = 16 >> st;
        const unsigned m = (st == 0) ? 0x0000FFFFu :
                           (st == 1) ? 0x00FF00FFu :
                           (st == 2) ? 0x0F0F0F0Fu :
                           (st == 3) ? 0x33333333u : 0x55555555u;
        unsigned y = __shfl_xor_sync(0xffffffffu, x, s);
        x = (lane & s) ? ((x & ~m) | ((y & ~m) >> s))
                       : ((x &  m) | ((y &  m) << s));
    }
    return x;
}

__global__ __launch_bounds__(NT)
void hist_kernel(const float* __restrict__ x, float* __restrict__ out) {
    __shared__ __align__(1024) float4 buf[STAGES][CHUNKB / 16];
    __shared__ __align__(8) unsigned long long mbar[STAGES];
    __shared__ unsigned swcnt[NT / 32][32];

    const int tid  = threadIdx.x;
    const int lane = tid & 31;
    const int warp = tid >> 5;
    const int row  = blockIdx.x;

    if (tid == 0) {
        #pragma unroll
        for (int s = 0; s < STAGES; s++)
            asm volatile("mbarrier.init.shared.b64 [%0], 1;"
                         :: "r"(smem_u32(&mbar[s])) : "memory");
        asm volatile("fence.proxy.async.shared::cta;" ::: "memory");
    }
    __syncthreads();

    const char* src = reinterpret_cast<const char*>(x + (size_t)row * COLS);

    // Prologue: fill the whole ring.
    if (tid == 0) {
        #pragma unroll
        for (int s = 0; s < STAGES; s++) {
            uint32_t mb = smem_u32(&mbar[s]);
            asm volatile("mbarrier.arrive.expect_tx.shared.b64 _, [%0], %1;"
                         :: "r"(mb), "r"(CHUNKB) : "memory");
            asm volatile(
                "cp.async.bulk.shared::cluster.global.mbarrier::complete_tx::bytes"
                " [%0], [%1], %2, [%3];"
                :: "r"(smem_u32(&buf[s][0])), "l"(src + s * CHUNKB),
                   "r"(CHUNKB), "r"(mb) : "memory");
        }
    }

    // 8 bit-plane counters, weights 1..128 (cap 255; 128 elem/thread -> safe)
    unsigned ones = 0, twos = 0, fours = 0;
    unsigned a8 = 0, a16 = 0, a32 = 0, a64 = 0, a128 = 0;

    #pragma unroll 1
    for (int c = 0; c < CHUNKS; c++) {
        const int s = c & (STAGES - 1);
        const unsigned parity = (c / STAGES) & 1u;
        const uint32_t mb = smem_u32(&mbar[s]);

        // Wait for TMA completion of stage s (acquire).
        asm volatile(
            "{\n\t.reg .pred P;\n"
            "W%=:\n\t"
            "mbarrier.try_wait.parity.acquire.cta.shared::cta.b64 P, [%0], %1, 0x989680;\n\t"
            "@P bra D%=;\n\t"
            "bra W%=;\n"
            "D%=:\n\t}"
            :: "r"(mb), "r"(parity) : "memory");

        // Consume 16 elems: 4x LDS.128, conflict-free (lane-contiguous).
        const float4* b = &buf[s][0];
        float4 va = b[tid];
        float4 vb = b[tid + 128];
        float4 vc = b[tid + 256];
        float4 vd = b[tid + 384];

        unsigned h0 = bin_onehot(va.x), h1 = bin_onehot(va.y);
        unsigned h2 = bin_onehot(va.z), h3 = bin_onehot(va.w);
        unsigned h4 = bin_onehot(vb.x), h5 = bin_onehot(vb.y);
        unsigned h6 = bin_onehot(vb.z), h7 = bin_onehot(vb.w);
        unsigned g0 = bin_onehot(vc.x), g1 = bin_onehot(vc.y);
        unsigned g2 = bin_onehot(vc.z), g3 = bin_onehot(vc.w);
        unsigned g4 = bin_onehot(vd.x), g5 = bin_onehot(vd.y);
        unsigned g6 = bin_onehot(vd.z), g7 = bin_onehot(vd.w);

        unsigned c2a, c2b, c4a, c4b, e8a, e8b;
        csa(ones, c2a, ones, h0, h1);
        csa(ones, c2b, ones, h2, h3);
        csa(twos, c4a, twos, c2a, c2b);
        csa(ones, c2a, ones, h4, h5);
        csa(ones, c2b, ones, h6, h7);
        csa(twos, c4b, twos, c2a, c2b);
        csa(fours, e8a, fours, c4a, c4b);
        csa(ones, c2a, ones, g0, g1);
        csa(ones, c2b, ones, g2, g3);
        csa(twos, c4a, twos, c2a, c2b);
        csa(ones, c2a, ones, g4, g5);
        csa(ones, c2b, ones, g6, g7);
        csa(twos, c4b, twos, c2a, c2b);
        csa(fours, e8b, fours, c4a, c4b);
        unsigned c16;
        csa(a8, c16, a8, e8a, e8b);
        unsigned cc = a16 & c16; a16 ^= c16;
        unsigned dd = a32 & cc;  a32 ^= cc;
        cc = a64 & dd;  a64  ^= dd;
        a128 ^= cc;

        // All threads done reading stage s -> safe to refill it.
        __syncthreads();
        if (tid == 0 && c + STAGES < CHUNKS) {
            asm volatile("mbarrier.arrive.expect_tx.shared.b64 _, [%0], %1;"
                         :: "r"(mb), "r"(CHUNKB) : "memory");
            asm volatile(
                "cp.async.bulk.shared::cluster.global.mbarrier::complete_tx::bytes"
                " [%0], [%1], %2, [%3];"
                :: "r"(smem_u32(&buf[s][0])), "l"(src + (c + STAGES) * CHUNKB),
                   "r"(CHUNKB), "r"(mb) : "memory");
        }
    }

    // Per-warp: transpose planes so lane b holds bin b; weighted popcounts.
    unsigned planes[8] = {ones, twos, fours, a8, a16, a32, a64, a128};
    unsigned cnt = 0;
    #pragma unroll
    for (int j = 0; j < 8; j++) {
        unsigned t = warp_bit_transpose(planes[j], lane);
        cnt += (unsigned)__popc(t) << j;
    }
    swcnt[warp][lane] = cnt;
    __syncthreads();
    if (warp == 0 && lane < NBINS) {
        unsigned total = swcnt[0][lane] + swcnt[1][lane]
                       + swcnt[2][lane] + swcnt[3][lane];
        int pos = (lane == 0) ? 0 : (lane == NBINS - 1) ? 1 : (lane + 1);
        out[(size_t)row * NBINS + pos] = (float)total;
    }
}

extern "C" void kernel_launch(void* const* d_in, const int* in_sizes, int n_in,
                              void* d_out, int out_size) {
    const float* x = (const float*)d_in[0];
    float* out = (float*)d_out;
    int rows = in_sizes[0] / COLS;
    hist_kernel<<<rows, NT>>>(x, out);
}